// round 4
// baseline (speedup 1.0000x reference)
#include <cuda_runtime.h>
#include <cuda_bf16.h>
#include <cstdint>

// Problem constants
#define TT   512
#define BB   64
#define HID  1024
#define LAY  4
#define NWAVE (TT + LAY - 1)   // 515

// fp32 hidden ring (epilogue z*h term + final output): 2 MB, L2-resident
__device__ float g_ring[2][LAY][BB][HID];
// packed split-bf16 activation fragments: [slot][l][b][kc 0..63][tig 0..3]
// uint4 = {hi(k0,k1), hi(k8,k9), lo(k0,k1), lo(k8,k9)}, k = kc*16 + {2tig,2tig+1, 8+2tig, 8+2tig+1}
__device__ uint4 g_apack[2][LAY][BB][64][4];            // 2 MB
// packed x fragments, same per-row layout: [t][b][kc][tig]
__device__ uint4 g_xpack[TT][BB][64][4];                // 33.5 MB
// packed split-bf16 weights, fragment-major: [m=l*2+s][kc][n 0..3071][tig]
__device__ uint4 g_wpack[8ull * 64 * 3072 * 4];         // 100.7 MB

// ---------- helpers ----------
__device__ __forceinline__ void split_pair(float x, float y, uint32_t& hi, uint32_t& lo) {
    __nv_bfloat16 hx = __float2bfloat16(x);
    __nv_bfloat16 hy = __float2bfloat16(y);
    float rx = x - __bfloat162float(hx);
    float ry = y - __bfloat162float(hy);
    __nv_bfloat162 H2; H2.x = hx; H2.y = hy;
    __nv_bfloat162 L2 = __floats2bfloat162_rn(rx, ry);
    hi = *reinterpret_cast<uint32_t*>(&H2);
    lo = *reinterpret_cast<uint32_t*>(&L2);
}

__device__ __forceinline__ void mma_bf16(float* c, const uint32_t* a, uint32_t b0, uint32_t b1) {
    asm volatile(
        "mma.sync.aligned.m16n8k16.row.col.f32.bf16.bf16.f32 "
        "{%0,%1,%2,%3},{%4,%5,%6,%7},{%8,%9},{%0,%1,%2,%3};"
        : "+f"(c[0]), "+f"(c[1]), "+f"(c[2]), "+f"(c[3])
        : "r"(a[0]), "r"(a[1]), "r"(a[2]), "r"(a[3]), "r"(b0), "r"(b1));
}

// ---------- weight packing (R2 fragment-major layout) ----------
__global__ void pack_weights_kernel(const float* __restrict__ w_ih,
                                    const float* __restrict__ w_hh) {
    int64_t idx = (int64_t)blockIdx.x * blockDim.x + threadIdx.x;
    const int64_t total = 8ll * 64 * 3072 * 4;
    if (idx >= total) return;
    int tig = (int)(idx & 3);
    int64_t t2 = idx >> 2;
    int n = (int)(t2 % 3072);
    int64_t t3 = t2 / 3072;
    int kc = (int)(t3 & 63);
    int m  = (int)(t3 >> 6);
    int l = m >> 1, s = m & 1;
    const float* src = (s ? w_hh : w_ih) + ((int64_t)l * 3072 + n) * 1024 + kc * 16 + 2 * tig;
    float f0 = src[0], f1 = src[1], f2 = src[8], f3 = src[9];
    uint4 q;
    split_pair(f0, f1, q.x, q.z);
    split_pair(f2, f3, q.y, q.w);
    g_wpack[idx] = q;
}

// ---------- x packing ----------
__global__ void pack_x_kernel(const float* __restrict__ x) {
    int64_t idx = (int64_t)blockIdx.x * blockDim.x + threadIdx.x;
    const int64_t total = (int64_t)TT * BB * 64 * 4;
    if (idx >= total) return;
    int tig = (int)(idx & 3);
    int kc  = (int)((idx >> 2) & 63);
    int b   = (int)((idx >> 8) & 63);
    int t   = (int)(idx >> 14);
    const float* src = x + ((int64_t)t * BB + b) * HID + kc * 16 + 2 * tig;
    uint4 q;
    split_pair(src[0], src[1], q.x, q.z);
    split_pair(src[8], src[9], q.y, q.w);
    g_xpack[t][b][kc][tig] = q;
}

// ---------- h0 init: fp32 ring + packed fragments ----------
__global__ void init_h0_kernel(const float* __restrict__ h0) {
    int idx = blockIdx.x * blockDim.x + threadIdx.x;   // < L*B*64*4 = 65536
    int tig = idx & 3;
    int kc  = (idx >> 2) & 63;
    int b   = (idx >> 8) & 63;
    int l   = idx >> 14;
    int slot = (l + 1) & 1;                            // read-slot of wave l
    const float* src = h0 + ((int64_t)l * BB + b) * HID + kc * 16 + 2 * tig;
    uint4 q;
    split_pair(src[0], src[1], q.x, q.z);
    split_pair(src[8], src[9], q.y, q.w);
    g_apack[slot][l][b][kc][tig] = q;
    // fp32 ring (4 scattered + 4 scattered writes, one-time cost)
    float* dst = &g_ring[slot][l][b][kc * 16 + 2 * tig];
    dst[0] = src[0]; dst[1] = src[1]; dst[8] = src[8]; dst[9] = src[9];
}

// ---------- wave kernel ----------
// grid = 256 (l = bx>>6, cb = bx&63 -> 16 cols), block = 512 threads (16 warps)
// warp = mstrip(0..3) x ksplit(0..1) x jsel(0..1)
//   mstrip: batch rows [16*mstrip, +16)
//   jsel  : which 8-col j-tile of the CTA's 16 cols
//   ksplit: K-half; per step = 3 gate-groups x 1 jt x 3 split-MMAs = 9 HMMA
__global__ void __launch_bounds__(512, 2)
wave_kernel(const float* __restrict__ b_ih,
            const float* __restrict__ b_hh,
            int w) {
    const int l  = blockIdx.x >> 6;
    const int cb = blockIdx.x & 63;
    const int t  = w - l;
    if (t < 0 || t >= TT) return;

    const int rs = (w + 1) & 1;   // read slot
    const int ws = w & 1;         // write slot

    const uint4* inp_pack = (l == 0) ? &g_xpack[t][0][0][0] : &g_apack[rs][l - 1][0][0][0];
    const uint4* h_pack   = &g_apack[rs][l][0][0][0];
    const float* hprev    = &g_ring[rs][l][0][0];
    float*       hout     = &g_ring[ws][l][0][0];

    const int lane = threadIdx.x & 31;
    const int warp = threadIdx.x >> 5;
    const int mstrip = warp & 3;
    const int ksplit = (warp >> 2) & 1;
    const int jsel   = warp >> 3;
    const int gid = lane >> 2;    // 0..7
    const int tig = lane & 3;     // 0..3
    const int c0 = cb * 16;

    // acc[group][reg]; groups: 0=r, 1=z, 2=gi_n, 3=gh_n
    float acc[4][4];
#pragma unroll
    for (int g = 0; g < 4; ++g)
#pragma unroll
        for (int r = 0; r < 4; ++r) acc[g][r] = 0.f;

    const int r0 = mstrip * 16 + gid;
    const int ncol = c0 + jsel * 8 + gid;      // weight row within gate block
    const int kc_lo = ksplit * 32;

#pragma unroll
    for (int phase = 0; phase < 2; ++phase) {
        const uint4* apack = phase ? h_pack : inp_pack;
        // A rows r0 and r0+8, frag tig, starting at kc_lo
        const uint4* pa0 = apack + (((int64_t)r0 * 64 + kc_lo) << 2) + tig;
        const uint4* pa1 = pa0 + ((int64_t)8 * 64 << 2);
        // B: [m][kc][n][tig]
        const uint4* pb = g_wpack
            + ((int64_t)(l * 2 + phase) * 64 + kc_lo) * (3072 * 4)
            + ((int64_t)ncol << 2) + tig;
        const int g_third = phase ? 3 : 2;

#pragma unroll 4
        for (int kk = 0; kk < 32; ++kk) {
            uint4 qa0 = pa0[kk << 2];
            uint4 qa1 = pa1[kk << 2];
            uint32_t Ah[4] = {qa0.x, qa1.x, qa0.y, qa1.y};
            uint32_t Al[4] = {qa0.z, qa1.z, qa0.w, qa1.w};

            const uint4* pbk = pb + (int64_t)kk * (3072 * 4);
#pragma unroll
            for (int gg = 0; gg < 3; ++gg) {
                const int g = (gg < 2) ? gg : g_third;
                uint4 q = pbk[gg * (HID * 4)];
                float* C = acc[g];
                mma_bf16(C, Ah, q.x, q.y);   // Ah * Wh
                mma_bf16(C, Ah, q.z, q.w);   // Ah * Wl
                mma_bf16(C, Al, q.x, q.y);   // Al * Wh
            }
        }
    }

    // ---- cross-warp K reduction through smem ----
    __shared__ float red[8][32][16];
    if (ksplit == 1) {
        const float* af = &acc[0][0];
        float* dst = &red[jsel * 4 + mstrip][lane][0];
#pragma unroll
        for (int i = 0; i < 16; ++i) dst[i] = af[i];
    }
    __syncthreads();
    if (ksplit == 1) return;
    {
        float* af = &acc[0][0];
        const float* srcr = &red[jsel * 4 + mstrip][lane][0];
#pragma unroll
        for (int i = 0; i < 16; ++i) af[i] += srcr[i];
    }

    // ---- gates + dual write (fp32 + packed split) ----
    const float* bi = b_ih + l * 3 * HID;
    const float* bh = b_hh + l * 3 * HID;
    // this thread's column pair: c = c0 + jsel*8 + tig*2 + par
    const int cpair = c0 + jsel * 8 + tig * 2;
#pragma unroll
    for (int half = 0; half < 2; ++half) {
        const int b = mstrip * 16 + gid + half * 8;
        float hnew[2];
#pragma unroll
        for (int par = 0; par < 2; ++par) {
            const int c = cpair + par;
            const int ri = half * 2 + par;
            float pr  = acc[0][ri] + bi[c]           + bh[c];
            float pz  = acc[1][ri] + bi[HID + c]     + bh[HID + c];
            float gin = acc[2][ri] + bi[2 * HID + c];
            float ghn = acc[3][ri] + bh[2 * HID + c];
            float rr = 1.f / (1.f + __expf(-pr));
            float zz = 1.f / (1.f + __expf(-pz));
            float nn = tanhf(gin + rr * ghn);
            float hp = hprev[(int64_t)b * HID + c];
            hnew[par] = (1.f - zz) * nn + zz * hp;
            hout[(int64_t)b * HID + c] = hnew[par];
        }
        // packed split write: kc = cb (since c0 = cb*16, jsel*8+tig*2 < 16)
        uint32_t hi, lo;
        split_pair(hnew[0], hnew[1], hi, lo);
        uint32_t* pp = reinterpret_cast<uint32_t*>(&g_apack[ws][l][b][cb][tig]);
        pp[jsel]     = hi;   // .x (k0k1) if jsel=0 else .y (k8k9)
        pp[2 + jsel] = lo;   // .z / .w
    }
}

// ---------- output copy ----------
__global__ void copy_out_kernel(float* __restrict__ out) {
    int idx = blockIdx.x * blockDim.x + threadIdx.x;   // < L*B*H
    int l = idx >> 16;
    int rest = idx & 0xFFFF;
    int slot = (TT - 1 + l) & 1;  // slot of layer l's final write (wave T-1+l)
    out[idx] = (&g_ring[slot][l][0][0])[rest];
}

// ---------- launch ----------
extern "C" void kernel_launch(void* const* d_in, const int* in_sizes, int n_in,
                              void* d_out, int out_size) {
    const float* x    = (const float*)d_in[0];
    const float* h0   = (const float*)d_in[1];
    const float* w_ih = (const float*)d_in[2];
    const float* w_hh = (const float*)d_in[3];
    const float* b_ih = (const float*)d_in[4];
    const float* b_hh = (const float*)d_in[5];
    float* out = (float*)d_out;

    // 1) pack weights
    {
        int64_t total = 8ll * 64 * 3072 * 4;
        pack_weights_kernel<<<(int)((total + 255) / 256), 256>>>(w_ih, w_hh);
    }
    // 2) pack x
    {
        int64_t total = (int64_t)TT * BB * 64 * 4;
        pack_x_kernel<<<(int)((total + 255) / 256), 256>>>(x);
    }
    // 3) h0 -> fp32 ring + packed fragments
    init_h0_kernel<<<(LAY * BB * 64 * 4) / 256, 256>>>(h0);

    // 4) wavefront: 515 dependent waves, stream-ordered
    for (int w = 0; w < NWAVE; ++w) {
        wave_kernel<<<256, 512>>>(b_ih, b_hh, w);
    }

    // 5) gather final hidden states
    copy_out_kernel<<<(LAY * BB * HID) / 256, 256>>>(out);
}

// round 5
// speedup vs baseline: 1.2883x; 1.2883x over previous
#include <cuda_runtime.h>
#include <cuda_bf16.h>
#include <cstdint>

// Problem constants
#define TT   512
#define BB   64
#define HID  1024
#define LAY  4
#define NWAVE (TT + LAY - 1)   // 515

// fp32 hidden ring (epilogue z*h term + final output): 2 MB, L2-resident
__device__ float g_ring[2][LAY][BB][HID];
// packed split-bf16 activation fragments: [slot][l][b][kc 0..63][tig 0..3]
// uint4 = {hi(k0,k1), hi(k8,k9), lo(k0,k1), lo(k8,k9)}, k = kc*16 + {2tig,2tig+1, 8+2tig, 9+2tig}
__device__ uint4 g_apack[2][LAY][BB][64][4];            // 2 MB
// packed x fragments, same per-row layout: [t][b][kc][tig]
__device__ uint4 g_xpack[TT][BB][64][4];                // 33.5 MB
// packed split-bf16 weights, fragment-major: [m=l*2+s][kc][n 0..3071][tig]
__device__ uint4 g_wpack[8ull * 64 * 3072 * 4];         // 100.7 MB

// ---------- helpers ----------
__device__ __forceinline__ void split_pair(float x, float y, uint32_t& hi, uint32_t& lo) {
    __nv_bfloat16 hx = __float2bfloat16(x);
    __nv_bfloat16 hy = __float2bfloat16(y);
    float rx = x - __bfloat162float(hx);
    float ry = y - __bfloat162float(hy);
    __nv_bfloat162 H2; H2.x = hx; H2.y = hy;
    __nv_bfloat162 L2 = __floats2bfloat162_rn(rx, ry);
    hi = *reinterpret_cast<uint32_t*>(&H2);
    lo = *reinterpret_cast<uint32_t*>(&L2);
}

__device__ __forceinline__ void mma_bf16(float* c, const uint32_t* a, uint32_t b0, uint32_t b1) {
    asm volatile(
        "mma.sync.aligned.m16n8k16.row.col.f32.bf16.bf16.f32 "
        "{%0,%1,%2,%3},{%4,%5,%6,%7},{%8,%9},{%0,%1,%2,%3};"
        : "+f"(c[0]), "+f"(c[1]), "+f"(c[2]), "+f"(c[3])
        : "r"(a[0]), "r"(a[1]), "r"(a[2]), "r"(a[3]), "r"(b0), "r"(b1));
}

// ---------- weight packing (fragment-major layout) ----------
__global__ void pack_weights_kernel(const float* __restrict__ w_ih,
                                    const float* __restrict__ w_hh) {
    int64_t idx = (int64_t)blockIdx.x * blockDim.x + threadIdx.x;
    const int64_t total = 8ll * 64 * 3072 * 4;
    if (idx >= total) return;
    int tig = (int)(idx & 3);
    int64_t t2 = idx >> 2;
    int n = (int)(t2 % 3072);
    int64_t t3 = t2 / 3072;
    int kc = (int)(t3 & 63);
    int m  = (int)(t3 >> 6);
    int l = m >> 1, s = m & 1;
    const float* src = (s ? w_hh : w_ih) + ((int64_t)l * 3072 + n) * 1024 + kc * 16 + 2 * tig;
    float f0 = src[0], f1 = src[1], f2 = src[8], f3 = src[9];
    uint4 q;
    split_pair(f0, f1, q.x, q.z);
    split_pair(f2, f3, q.y, q.w);
    g_wpack[idx] = q;
}

// ---------- x packing ----------
__global__ void pack_x_kernel(const float* __restrict__ x) {
    int64_t idx = (int64_t)blockIdx.x * blockDim.x + threadIdx.x;
    const int64_t total = (int64_t)TT * BB * 64 * 4;
    if (idx >= total) return;
    int tig = (int)(idx & 3);
    int kc  = (int)((idx >> 2) & 63);
    int b   = (int)((idx >> 8) & 63);
    int t   = (int)(idx >> 14);
    const float* src = x + ((int64_t)t * BB + b) * HID + kc * 16 + 2 * tig;
    uint4 q;
    split_pair(src[0], src[1], q.x, q.z);
    split_pair(src[8], src[9], q.y, q.w);
    g_xpack[t][b][kc][tig] = q;
}

// ---------- h0 init: fp32 ring + packed fragments ----------
__global__ void init_h0_kernel(const float* __restrict__ h0) {
    int idx = blockIdx.x * blockDim.x + threadIdx.x;   // < L*B*64*4 = 65536
    int tig = idx & 3;
    int kc  = (idx >> 2) & 63;
    int b   = (idx >> 8) & 63;
    int l   = idx >> 14;
    int slot = (l + 1) & 1;                            // read-slot of wave l
    const float* src = h0 + ((int64_t)l * BB + b) * HID + kc * 16 + 2 * tig;
    uint4 q;
    split_pair(src[0], src[1], q.x, q.z);
    split_pair(src[8], src[9], q.y, q.w);
    g_apack[slot][l][b][kc][tig] = q;
    float* dst = &g_ring[slot][l][b][kc * 16 + 2 * tig];
    dst[0] = src[0]; dst[1] = src[1]; dst[8] = src[8]; dst[9] = src[9];
}

// ---------- wave kernel ----------
// grid = 128 (l = bx>>5, cb = bx&31 -> 32 cols), block = 512 threads (16 warps)
// warp = mstrip(0..3) x ksplit(0..1) x jhalf(0..1)
//   mstrip: batch rows [16*mstrip, +16);  jhalf: jt in {2*jhalf, 2*jhalf+1}
//   ksplit: K-half; per step = 2 A-loads + 6 B-loads + 18 HMMA (term-major order)
__global__ void __launch_bounds__(512, 1)
wave_kernel(const float* __restrict__ b_ih,
            const float* __restrict__ b_hh,
            int w) {
    const int l  = blockIdx.x >> 5;
    const int cb = blockIdx.x & 31;
    const int t  = w - l;
    if (t < 0 || t >= TT) return;

    const int rs = (w + 1) & 1;   // read slot
    const int ws = w & 1;         // write slot

    const uint4* inp_pack = (l == 0) ? &g_xpack[t][0][0][0] : &g_apack[rs][l - 1][0][0][0];
    const uint4* h_pack   = &g_apack[rs][l][0][0][0];
    const float* hprev    = &g_ring[rs][l][0][0];
    float*       hout     = &g_ring[ws][l][0][0];

    const int lane = threadIdx.x & 31;
    const int warp = threadIdx.x >> 5;
    const int mstrip = warp & 3;
    const int ksplit = (warp >> 2) & 1;
    const int jhalf  = warp >> 3;
    const int gid = lane >> 2;    // 0..7
    const int tig = lane & 3;     // 0..3
    const int c0 = cb * 32;

    // acc[group][jtl][reg]; groups: 0=r, 1=z, 2=gi_n, 3=gh_n
    float acc[4][2][4];
#pragma unroll
    for (int g = 0; g < 4; ++g)
#pragma unroll
        for (int j = 0; j < 2; ++j)
#pragma unroll
            for (int r = 0; r < 4; ++r) acc[g][j][r] = 0.f;

    const int r0 = mstrip * 16 + gid;
    const int kc_lo = ksplit * 32;
    const int nbase = c0 + jhalf * 16 + gid;   // + gg*1024 + jtl*8

#pragma unroll
    for (int phase = 0; phase < 2; ++phase) {
        const uint4* apack = phase ? h_pack : inp_pack;
        const uint4* pa0 = apack + (((int64_t)r0 * 64 + kc_lo) << 2) + tig;
        const uint4* pa1 = pa0 + ((int64_t)8 * 64 << 2);
        const uint4* pb = g_wpack
            + ((int64_t)(l * 2 + phase) * 64 + kc_lo) * (3072 * 4)
            + ((int64_t)nbase << 2) + tig;
        const int g_third = phase ? 3 : 2;

#pragma unroll 2
        for (int kk = 0; kk < 32; ++kk) {
            uint4 qa0 = pa0[kk << 2];
            uint4 qa1 = pa1[kk << 2];
            uint32_t Ah[4] = {qa0.x, qa1.x, qa0.y, qa1.y};
            uint32_t Al[4] = {qa0.z, qa1.z, qa0.w, qa1.w};

            const uint4* pbk = pb + (int64_t)kk * (3072 * 4);
            uint4 qb[3][2];
#pragma unroll
            for (int gg = 0; gg < 3; ++gg)
#pragma unroll
                for (int jtl = 0; jtl < 2; ++jtl)
                    qb[gg][jtl] = pbk[(gg * HID + jtl * 8) << 2];

            // term-major MMA order: same-C MMAs spaced 6 apart
#pragma unroll
            for (int gg = 0; gg < 3; ++gg) {
                const int g = (gg < 2) ? gg : g_third;
#pragma unroll
                for (int jtl = 0; jtl < 2; ++jtl)
                    mma_bf16(acc[g][jtl], Ah, qb[gg][jtl].x, qb[gg][jtl].y);  // Ah*Whi
            }
#pragma unroll
            for (int gg = 0; gg < 3; ++gg) {
                const int g = (gg < 2) ? gg : g_third;
#pragma unroll
                for (int jtl = 0; jtl < 2; ++jtl)
                    mma_bf16(acc[g][jtl], Ah, qb[gg][jtl].z, qb[gg][jtl].w);  // Ah*Wlo
            }
#pragma unroll
            for (int gg = 0; gg < 3; ++gg) {
                const int g = (gg < 2) ? gg : g_third;
#pragma unroll
                for (int jtl = 0; jtl < 2; ++jtl)
                    mma_bf16(acc[g][jtl], Al, qb[gg][jtl].x, qb[gg][jtl].y);  // Al*Whi
            }
        }
    }

    // ---- cross-warp K reduction through smem ----
    __shared__ float red[8][32][32];
    if (ksplit == 1) {
        const float* af = &acc[0][0][0];
        float* dst = &red[jhalf * 4 + mstrip][lane][0];
#pragma unroll
        for (int i = 0; i < 32; ++i) dst[i] = af[i];
    }
    __syncthreads();
    if (ksplit == 1) return;
    {
        float* af = &acc[0][0][0];
        const float* srcr = &red[jhalf * 4 + mstrip][lane][0];
#pragma unroll
        for (int i = 0; i < 32; ++i) af[i] += srcr[i];
    }

    // ---- gates + dual write (fp32 ring + packed split fragments) ----
    const float* bi = b_ih + l * 3 * HID;
    const float* bh = b_hh + l * 3 * HID;
#pragma unroll
    for (int jtl = 0; jtl < 2; ++jtl) {
        const int jt = jhalf * 2 + jtl;
        const int jbase = jt * 8 + tig * 2;
#pragma unroll
        for (int half = 0; half < 2; ++half) {
            const int b = mstrip * 16 + gid + half * 8;
            float hnew[2];
#pragma unroll
            for (int par = 0; par < 2; ++par) {
                const int c = c0 + jbase + par;
                const int ri = half * 2 + par;
                float pr  = acc[0][jtl][ri] + bi[c]           + bh[c];
                float pz  = acc[1][jtl][ri] + bi[HID + c]     + bh[HID + c];
                float gin = acc[2][jtl][ri] + bi[2 * HID + c];
                float ghn = acc[3][jtl][ri] + bh[2 * HID + c];
                float rr = 1.f / (1.f + __expf(-pr));
                float zz = 1.f / (1.f + __expf(-pz));
                float nn = tanhf(gin + rr * ghn);
                float hp = hprev[(int64_t)b * HID + c];
                hnew[par] = (1.f - zz) * nn + zz * hp;
                hout[(int64_t)b * HID + c] = hnew[par];
            }
            // packed split write: kc_out = cb*2 + jhalf; word jtl (k0k1) / 2+jtl
            uint32_t hi, lo;
            split_pair(hnew[0], hnew[1], hi, lo);
            uint32_t* pp = reinterpret_cast<uint32_t*>(&g_apack[ws][l][b][cb * 2 + jhalf][tig]);
            pp[jtl]     = hi;
            pp[2 + jtl] = lo;
        }
    }
}

// ---------- output copy ----------
__global__ void copy_out_kernel(float* __restrict__ out) {
    int idx = blockIdx.x * blockDim.x + threadIdx.x;   // < L*B*H
    int l = idx >> 16;
    int rest = idx & 0xFFFF;
    int slot = (TT - 1 + l) & 1;  // slot of layer l's final write (wave T-1+l)
    out[idx] = (&g_ring[slot][l][0][0])[rest];
}

// ---------- launch ----------
extern "C" void kernel_launch(void* const* d_in, const int* in_sizes, int n_in,
                              void* d_out, int out_size) {
    const float* x    = (const float*)d_in[0];
    const float* h0   = (const float*)d_in[1];
    const float* w_ih = (const float*)d_in[2];
    const float* w_hh = (const float*)d_in[3];
    const float* b_ih = (const float*)d_in[4];
    const float* b_hh = (const float*)d_in[5];
    float* out = (float*)d_out;

    // 1) pack weights
    {
        int64_t total = 8ll * 64 * 3072 * 4;
        pack_weights_kernel<<<(int)((total + 255) / 256), 256>>>(w_ih, w_hh);
    }
    // 2) pack x
    {
        int64_t total = (int64_t)TT * BB * 64 * 4;
        pack_x_kernel<<<(int)((total + 255) / 256), 256>>>(x);
    }
    // 3) h0 -> fp32 ring + packed fragments
    init_h0_kernel<<<(LAY * BB * 64 * 4) / 256, 256>>>(h0);

    // 4) wavefront: 515 dependent waves, stream-ordered
    for (int w = 0; w < NWAVE; ++w) {
        wave_kernel<<<128, 512>>>(b_ih, b_hh, w);
    }

    // 5) gather final hidden states
    copy_out_kernel<<<(LAY * BB * HID) / 256, 256>>>(out);
}

// round 6
// speedup vs baseline: 2.8143x; 2.1845x over previous
#include <cuda_runtime.h>
#include <cuda_fp16.h>
#include <cstdint>

// Problem constants
#define TT   512
#define BB   64
#define HID  1024
#define LAY  4
#define NWAVE (TT + LAY - 1)   // 515

// fp32 hidden ring (epilogue z*h term + final output): 2 MB, L2-resident
__device__ float g_ring[2][LAY][BB][HID];

// fp16 activation fragments: [slot][l][bpair 0..31][kc 0..63][tig 0..3] -> uint4
// bpair p: rows ra = (p>>3)*16 + (p&7), rb = ra+8
// uint4 = {ra:k0k1, rb:k0k1, ra:k8k9, rb:k8k9}  (exact A-fragment register order)
__device__ uint4 g_apack16[2][LAY][32][64][4];          // 1 MB

// fp16 x fragments, same per-(bpair,kc,tig) layout: [t][bpair][kc][tig]
__device__ uint4 g_xpack16[TT][32][64][4];              // 16.8 MB

// fp16 weights: [m=l*2+s][kc][gg][p 0..511][tig] -> uint4
// p: rows (within gate block) ra = (p>>3)*16 + (p&7), rb = ra+8
// uint4 = {ra:k0k1, ra:k8k9, rb:k0k1, rb:k8k9}  (B-frag: jtl0 uses .x.y, jtl1 uses .z.w)
__device__ uint4 g_wpack16[8ull * 64 * 3 * 512 * 4];    // 50.3 MB

// ---------- helpers ----------
__device__ __forceinline__ uint32_t f2h2(float x, float y) {
    __half2 h = __floats2half2_rn(x, y);
    return *reinterpret_cast<uint32_t*>(&h);
}

__device__ __forceinline__ void mma_fp16(float* c, const uint32_t* a, uint32_t b0, uint32_t b1) {
    asm volatile(
        "mma.sync.aligned.m16n8k16.row.col.f32.f16.f16.f32 "
        "{%0,%1,%2,%3},{%4,%5,%6,%7},{%8,%9},{%0,%1,%2,%3};"
        : "+f"(c[0]), "+f"(c[1]), "+f"(c[2]), "+f"(c[3])
        : "r"(a[0]), "r"(a[1]), "r"(a[2]), "r"(a[3]), "r"(b0), "r"(b1));
}

// ---------- weight packing (fp16, row-pair fragment layout) ----------
__global__ void pack_weights16_kernel(const float* __restrict__ w_ih,
                                      const float* __restrict__ w_hh) {
    int64_t idx = (int64_t)blockIdx.x * blockDim.x + threadIdx.x;
    const int64_t total = 8ll * 64 * 3 * 512 * 4;
    if (idx >= total) return;
    int tig = (int)(idx & 3);
    int64_t t2 = idx >> 2;
    int p  = (int)(t2 & 511);  t2 >>= 9;
    int gg = (int)(t2 % 3);    t2 /= 3;
    int kc = (int)(t2 & 63);
    int m  = (int)(t2 >> 6);
    int l = m >> 1, s = m & 1;
    int ra = gg * HID + (p >> 3) * 16 + (p & 7);
    const float* base = (s ? w_hh : w_ih) + (int64_t)l * 3072 * 1024;
    const float* sa = base + (int64_t)ra * 1024 + kc * 16 + 2 * tig;
    const float* sb = sa + 8 * 1024;   // row +8
    uint4 q;
    q.x = f2h2(sa[0], sa[1]);   // ra k0k1
    q.y = f2h2(sa[8], sa[9]);   // ra k8k9
    q.z = f2h2(sb[0], sb[1]);   // rb k0k1
    q.w = f2h2(sb[8], sb[9]);   // rb k8k9
    g_wpack16[idx] = q;
}

// ---------- x packing ----------
__global__ void pack_x16_kernel(const float* __restrict__ x) {
    int64_t idx = (int64_t)blockIdx.x * blockDim.x + threadIdx.x;
    const int64_t total = (int64_t)TT * 32 * 64 * 4;
    if (idx >= total) return;
    int tig   = (int)(idx & 3);
    int kc    = (int)((idx >> 2) & 63);
    int bpair = (int)((idx >> 8) & 31);
    int t     = (int)(idx >> 13);
    int ba = (bpair >> 3) * 16 + (bpair & 7);
    const float* sa = x + ((int64_t)t * BB + ba) * HID + kc * 16 + 2 * tig;
    const float* sb = sa + 8 * HID;    // row +8
    uint4 q;
    q.x = f2h2(sa[0], sa[1]);   // ra k0k1
    q.y = f2h2(sb[0], sb[1]);   // rb k0k1
    q.z = f2h2(sa[8], sa[9]);   // ra k8k9
    q.w = f2h2(sb[8], sb[9]);   // rb k8k9
    g_xpack16[t][bpair][kc][tig] = q;
}

// ---------- h0 init: fp32 ring + fp16 fragments ----------
__global__ void init_h0_kernel(const float* __restrict__ h0) {
    int idx = blockIdx.x * blockDim.x + threadIdx.x;   // < L*32*64*4 = 32768
    int tig   = idx & 3;
    int kc    = (idx >> 2) & 63;
    int bpair = (idx >> 8) & 31;
    int l     = idx >> 13;
    int slot = (l + 1) & 1;                            // read-slot of wave l
    int ba = (bpair >> 3) * 16 + (bpair & 7);
    const float* sa = h0 + ((int64_t)l * BB + ba) * HID + kc * 16 + 2 * tig;
    const float* sb = sa + 8 * HID;
    uint4 q;
    q.x = f2h2(sa[0], sa[1]);
    q.y = f2h2(sb[0], sb[1]);
    q.z = f2h2(sa[8], sa[9]);
    q.w = f2h2(sb[8], sb[9]);
    g_apack16[slot][l][bpair][kc][tig] = q;
    float* da = &g_ring[slot][l][ba][kc * 16 + 2 * tig];
    float* db = da + 8 * HID;
    da[0] = sa[0]; da[1] = sa[1]; da[8] = sa[8]; da[9] = sa[9];
    db[0] = sb[0]; db[1] = sb[1]; db[8] = sb[8]; db[9] = sb[9];
}

// ---------- wave kernel ----------
// grid = 128 (l = bx>>5, cb = bx&31 -> 32 cols), block = 512 threads (16 warps)
// warp = mstrip(0..3) x ksplit(0..1) x jhalf(0..1)
// per step: 1 A-load + 3 B-loads + 6 HMMA (fp16 single-pass)
__global__ void __launch_bounds__(512, 1)
wave_kernel(const float* __restrict__ b_ih,
            const float* __restrict__ b_hh,
            int w) {
    const int l  = blockIdx.x >> 5;
    const int cb = blockIdx.x & 31;
    const int t  = w - l;
    if (t < 0 || t >= TT) return;

    const int rs = (w + 1) & 1;   // read slot
    const int ws = w & 1;         // write slot

    const uint4* inp_pack = (l == 0) ? &g_xpack16[t][0][0][0] : &g_apack16[rs][l - 1][0][0][0];
    const uint4* h_pack   = &g_apack16[rs][l][0][0][0];
    const float* hprev    = &g_ring[rs][l][0][0];
    float*       hout     = &g_ring[ws][l][0][0];

    const int lane = threadIdx.x & 31;
    const int warp = threadIdx.x >> 5;
    const int mstrip = warp & 3;
    const int ksplit = (warp >> 2) & 1;
    const int jhalf  = warp >> 3;
    const int gid = lane >> 2;    // 0..7
    const int tig = lane & 3;     // 0..3
    const int c0 = cb * 32;

    // acc[group][jtl][reg]; groups: 0=r, 1=z, 2=gi_n, 3=gh_n
    float acc[4][2][4];
#pragma unroll
    for (int g = 0; g < 4; ++g)
#pragma unroll
        for (int j = 0; j < 2; ++j)
#pragma unroll
            for (int r = 0; r < 4; ++r) acc[g][j][r] = 0.f;

    const int bpair = mstrip * 8 + gid;                  // A row-pair index
    const int pidx  = (cb * 2 + jhalf) * 8 + gid;        // B row-pair index (within gate block)
    const int kc_lo = ksplit * 32;

#pragma unroll
    for (int phase = 0; phase < 2; ++phase) {
        const uint4* apack = phase ? h_pack : inp_pack;
        const uint4* pa = apack + (((int64_t)bpair * 64 + kc_lo) << 2) + tig;
        // B: [m][kc][gg][p][tig]
        const uint4* pb = g_wpack16
            + ((((int64_t)(l * 2 + phase) * 64 + kc_lo) * 3) * 512 + pidx) * 4 + tig;
        const int g_third = phase ? 3 : 2;

#pragma unroll 4
        for (int kk = 0; kk < 32; ++kk) {
            uint4 qa = pa[kk << 2];
            uint32_t Ah[4] = {qa.x, qa.y, qa.z, qa.w};

            const uint4* pbk = pb + (int64_t)kk * (3 * 512 * 4);
            uint4 qb0 = pbk[0];
            uint4 qb1 = pbk[512 * 4];
            uint4 qb2 = pbk[2 * 512 * 4];

            mma_fp16(acc[0][0],       Ah, qb0.x, qb0.y);
            mma_fp16(acc[0][1],       Ah, qb0.z, qb0.w);
            mma_fp16(acc[1][0],       Ah, qb1.x, qb1.y);
            mma_fp16(acc[1][1],       Ah, qb1.z, qb1.w);
            mma_fp16(acc[g_third][0], Ah, qb2.x, qb2.y);
            mma_fp16(acc[g_third][1], Ah, qb2.z, qb2.w);
        }
    }

    // ---- cross-warp K reduction through smem ----
    __shared__ float red[8][32][32];
    if (ksplit == 1) {
        const float* af = &acc[0][0][0];
        float* dst = &red[jhalf * 4 + mstrip][lane][0];
#pragma unroll
        for (int i = 0; i < 32; ++i) dst[i] = af[i];
    }
    __syncthreads();
    if (ksplit == 1) return;
    {
        float* af = &acc[0][0][0];
        const float* srcr = &red[jhalf * 4 + mstrip][lane][0];
#pragma unroll
        for (int i = 0; i < 32; ++i) af[i] += srcr[i];
    }

    // ---- gates + dual write (fp32 ring + assembled fp16 fragment uint4) ----
    const float* bi = b_ih + l * 3 * HID;
    const float* bh = b_hh + l * 3 * HID;
    uint32_t frag[4];   // [jtl*2 + half] -> {x,y,z,w} of apack uint4
#pragma unroll
    for (int jtl = 0; jtl < 2; ++jtl) {
        const int jt = jhalf * 2 + jtl;
        const int jbase = jt * 8 + tig * 2;
#pragma unroll
        for (int half = 0; half < 2; ++half) {
            const int b = mstrip * 16 + gid + half * 8;
            float hnew[2];
#pragma unroll
            for (int par = 0; par < 2; ++par) {
                const int c = c0 + jbase + par;
                const int ri = half * 2 + par;
                float pr  = acc[0][jtl][ri] + bi[c]           + bh[c];
                float pz  = acc[1][jtl][ri] + bi[HID + c]     + bh[HID + c];
                float gin = acc[2][jtl][ri] + bi[2 * HID + c];
                float ghn = acc[3][jtl][ri] + bh[2 * HID + c];
                float rr = 1.f / (1.f + __expf(-pr));
                float zz = 1.f / (1.f + __expf(-pz));
                float nn = tanhf(gin + rr * ghn);
                float hp = hprev[(int64_t)b * HID + c];
                hnew[par] = (1.f - zz) * nn + zz * hp;
                hout[(int64_t)b * HID + c] = hnew[par];
            }
            frag[jtl * 2 + half] = f2h2(hnew[0], hnew[1]);
        }
    }
    // layout: {ra:k0k1, rb:k0k1, ra:k8k9, rb:k8k9}
    // jtl0 = k0k1 (jt even -> col offset < 8), jtl1 = k8k9; half0 = ra, half1 = rb
    {
        uint4 q;
        q.x = frag[0];   // jtl0, half0
        q.y = frag[1];   // jtl0, half1
        q.z = frag[2];   // jtl1, half0
        q.w = frag[3];   // jtl1, half1
        const int kc_out = cb * 2 + jhalf;
        g_apack16[ws][l][bpair][kc_out][tig] = q;
    }
}

// ---------- output copy ----------
__global__ void copy_out_kernel(float* __restrict__ out) {
    int idx = blockIdx.x * blockDim.x + threadIdx.x;   // < L*B*H
    int l = idx >> 16;
    int rest = idx & 0xFFFF;
    int slot = (TT - 1 + l) & 1;  // slot of layer l's final write (wave T-1+l)
    out[idx] = (&g_ring[slot][l][0][0])[rest];
}

// ---------- launch ----------
extern "C" void kernel_launch(void* const* d_in, const int* in_sizes, int n_in,
                              void* d_out, int out_size) {
    const float* x    = (const float*)d_in[0];
    const float* h0   = (const float*)d_in[1];
    const float* w_ih = (const float*)d_in[2];
    const float* w_hh = (const float*)d_in[3];
    const float* b_ih = (const float*)d_in[4];
    const float* b_hh = (const float*)d_in[5];
    float* out = (float*)d_out;

    // 1) pack weights (fp16)
    {
        int64_t total = 8ll * 64 * 3 * 512 * 4;
        pack_weights16_kernel<<<(int)((total + 255) / 256), 256>>>(w_ih, w_hh);
    }
    // 2) pack x (fp16)
    {
        int64_t total = (int64_t)TT * 32 * 64 * 4;
        pack_x16_kernel<<<(int)((total + 255) / 256), 256>>>(x);
    }
    // 3) h0 -> fp32 ring + fp16 fragments
    init_h0_kernel<<<(LAY * 32 * 64 * 4) / 256, 256>>>(h0);

    // 4) wavefront: 515 dependent waves, stream-ordered
    for (int w = 0; w < NWAVE; ++w) {
        wave_kernel<<<128, 512>>>(b_ih, b_hh, w);
    }

    // 5) gather final hidden states
    copy_out_kernel<<<(LAY * BB * HID) / 256, 256>>>(out);
}